// round 4
// baseline (speedup 1.0000x reference)
#include <cuda_runtime.h>
#include <math.h>

#define Dd 2048
#define Hh 1152
#define Kk 64
#define NAa 18
#define Rr 10

// ---------------- scratch (device globals) ----------------------------------
__device__ __align__(16) float d_s[Dd];
__device__ __align__(16) float d_u[Hh];
__device__ __align__(16) float d_ghat[Dd];
__device__ __align__(16) float d_gpart[4 * Dd];   // Whh_m@h_t + biases
__device__ __align__(16) float d_T[NAa * Dd];     // u_resh @ Wphi
__device__ float d_part_sq[1024];
__device__ float d_part_mv[1024];
__device__ float d_cosv[Rr];
__device__ float d_wval;

__device__ __forceinline__ float sigm(float x) { return 1.f / (1.f + expf(-x)); }

// warp dot over NIT*32 float4s (lane-strided), result on all lanes
template <int NIT>
__device__ __forceinline__ float wdot(const float4* __restrict__ a,
                                      const float4* __restrict__ b, int lane) {
    float acc = 0.f;
#pragma unroll
    for (int i = 0; i < NIT; i++) {
        float4 x = a[lane + i * 32];
        float4 y = b[lane + i * 32];
        acc = fmaf(x.x, y.x, acc);
        acc = fmaf(x.y, y.y, acc);
        acc = fmaf(x.z, y.z, acc);
        acc = fmaf(x.w, y.w, acc);
    }
#pragma unroll
    for (int o = 16; o; o >>= 1) acc += __shfl_xor_sync(0xffffffffu, acc, o);
    return acc;
}

// ---------------- Wave A -----------------------------------------------------
// blocks [0,256):    s rows, 1 row/warp
// blocks [256,832):  worker gate rows, 1 row/warp, 2 units/block
// blocks [832,1856): Whh_m rows -> d_gpart, 1 row/warp
__global__ void __launch_bounds__(256)
kA(const float* __restrict__ x, const float* __restrict__ Wp,
   const float* __restrict__ bp, const float* __restrict__ Wms,
   const float* __restrict__ bms, const float* __restrict__ Wih_w,
   const float* __restrict__ Whh_w, const float* __restrict__ bih_w,
   const float* __restrict__ bhh_w, const float* __restrict__ hn_w,
   const float* __restrict__ cn_w, const float* __restrict__ Whh_m,
   const float* __restrict__ bih_m, const float* __restrict__ bhh_m,
   const float* __restrict__ hn_m, const int* __restrict__ tickp) {
    const int warp = threadIdx.x >> 5, lane = threadIdx.x & 31;
    const int b = blockIdx.x;
    __shared__ __align__(16) float zs[Dd];
    __shared__ float gsh[8];

    if (b < 832) {
        // z = relu(Wp@x + bp) recomputed into smem
        float x0 = x[0], x1 = x[1];
        for (int i = threadIdx.x; i < Dd; i += 256) {
            float v = fmaf(Wp[2 * i], x0, fmaf(Wp[2 * i + 1], x1, bp[i]));
            zs[i] = fmaxf(v, 0.f);
        }
        __syncthreads();
        if (b < 256) {
            int row = b * 8 + warp;
            float v = wdot<16>((const float4*)(Wms + (size_t)row * Dd),
                               (const float4*)zs, lane);
            if (!lane) d_s[row] = fmaxf(v + bms[row], 0.f);
        } else {
            const int wb = b - 256;
            const int unit = wb * 2 + (warp >> 2);
            const int q = warp & 3;
            const int row = unit + q * Hh;
            float a = wdot<16>((const float4*)(Wih_w + (size_t)row * Dd),
                               (const float4*)zs, lane);
            float c = wdot<9>((const float4*)(Whh_w + (size_t)row * Hh),
                              (const float4*)hn_w, lane);
            if (!lane) gsh[warp] = a + c + bih_w[row] + bhh_w[row];
            __syncthreads();
            if ((threadIdx.x & 127) == 0) {
                const int half = threadIdx.x >> 7;
                const int j = wb * 2 + half;
                const float* g = gsh + half * 4;
                float ig = sigm(g[0]), fg = sigm(g[1]);
                float g2 = tanhf(g[2]), og = sigm(g[3]);
                float c2 = fmaf(fg, cn_w[j], ig * g2);
                d_u[j] = og * tanhf(c2);
            }
        }
    } else {
        const int row = (b - 832) * 8 + warp;
        const int tick = *tickp;
        float v = wdot<16>((const float4*)(Whh_m + (size_t)row * Dd),
                           (const float4*)(hn_m + (size_t)tick * Dd), lane);
        if (!lane) d_gpart[row] = v + bih_m[row] + bhh_m[row];
    }
}

// ---------------- Wave B -----------------------------------------------------
// blocks [0,1024):     manager gate rows (1/warp, 2 units/block) -> ghat, partials
// blocks [1024,1042):  T row a = b-1024
// block  1042:         cosines r=0..8
// block  1043:         w_value
__global__ void __launch_bounds__(256)
kB(const float* __restrict__ Wih_m, const float* __restrict__ hn_m,
   const float* __restrict__ cn_m, const float* __restrict__ Wmv,
   const float* __restrict__ Wphi, const float* __restrict__ goals,
   const float* __restrict__ states, const float* __restrict__ Wc,
   const float* __restrict__ bc, const int* __restrict__ tickp) {
    const int tid = threadIdx.x;
    const int warp = tid >> 5, lane = tid & 31;
    const int b = blockIdx.x;

    if (b < 1024) {
        const int unit = b * 2 + (warp >> 2);
        const int q = warp & 3;
        const int row = unit + q * Dd;
        float v = wdot<16>((const float4*)(Wih_m + (size_t)row * Dd),
                           (const float4*)d_s, lane) + d_gpart[row];
        __shared__ float gsh[8];
        __shared__ float pp[4];
        if (!lane) gsh[warp] = v;
        __syncthreads();
        if ((tid & 127) == 0) {
            const int half = tid >> 7;
            const int i = b * 2 + half;
            const int tick = *tickp;
            const float* g = gsh + half * 4;
            float ig = sigm(g[0]), fg = sigm(g[1]);
            float g2 = tanhf(g[2]), og = sigm(g[3]);
            float c2 = fmaf(fg, cn_m[(size_t)tick * Dd + i], ig * g2);
            float hnew = og * tanhf(c2);
            float hs = hnew;
#pragma unroll
            for (int r = 0; r < Rr; r++)
                if (r != tick) hs += hn_m[(size_t)r * Dd + i];
            float gh = hs * 0.1f;
            d_ghat[i] = gh;
            pp[half * 2] = gh * gh;
            pp[half * 2 + 1] = gh * Wmv[i];
        }
        __syncthreads();
        if (tid == 0) {
            d_part_sq[b] = pp[0] + pp[2];
            d_part_mv[b] = pp[1] + pp[3];
        }
    } else if (b < 1024 + NAa) {
        const int a = b - 1024;
        __shared__ float us[Kk];
        if (tid < Kk) us[tid] = d_u[a * Kk + tid];
        __syncthreads();
        for (int d = tid; d < Dd; d += 256) {
            float acc = 0.f;
#pragma unroll
            for (int k = 0; k < Kk; k++)
                acc = fmaf(us[k], Wphi[(size_t)k * Dd + d], acc);
            d_T[(size_t)a * Dd + d] = acc;
        }
    } else if (b == 1024 + NAa) {
        for (int r = warp; r < Rr - 1; r += 8) {
            const float* st = states + (size_t)(r + 1) * Dd;
            const float* gl = goals + (size_t)(r + 1) * Dd;
            float num = 0.f, dd = 0.f, gg = 0.f;
            for (int d = lane; d < Dd; d += 32) {
                float diff = d_s[d] - st[d];
                float go = gl[d];
                num = fmaf(diff, go, num);
                dd = fmaf(diff, diff, dd);
                gg = fmaf(go, go, gg);
            }
#pragma unroll
            for (int o = 16; o; o >>= 1) {
                num += __shfl_xor_sync(0xffffffffu, num, o);
                dd += __shfl_xor_sync(0xffffffffu, dd, o);
                gg += __shfl_xor_sync(0xffffffffu, gg, o);
            }
            if (!lane)
                d_cosv[r] = num / (fmaxf(sqrtf(dd), 1e-8f) *
                                   fmaxf(sqrtf(gg), 1e-8f));
        }
    } else {
        __shared__ float red[256];
        float wv = 0.f;
        for (int j = tid; j < Hh; j += 256) wv = fmaf(d_u[j], Wc[j], wv);
        red[tid] = wv;
        __syncthreads();
        for (int s = 128; s; s >>= 1) {
            if (tid < s) red[tid] += red[tid + s];
            __syncthreads();
        }
        if (tid == 0) d_wval = red[0] + bc[0];
    }
}

// ---------------- K4: final (1 block, 640 threads) ---------------------------
// out: [0:18] logits, [18] intrinsic, [19] w_value, [20] m_value
__global__ void __launch_bounds__(640)
k4_final(const float* __restrict__ goals, const float* __restrict__ states,
         const float* __restrict__ bmv, float* __restrict__ out) {
    const int tid = threadIdx.x;
    const int warp = tid >> 5, lane = tid & 31;
    __shared__ float wsum[20], wsum2[20];
    __shared__ float sc[4];
    __shared__ __align__(16) float gsum[Dd];

    // reduce 1024 partials (sq and mv) deterministically
    {
        float a = 0.f, c = 0.f;
        for (int i = tid; i < 1024; i += 640) {
            a += d_part_sq[i];
            c += d_part_mv[i];
        }
#pragma unroll
        for (int o = 16; o; o >>= 1) {
            a += __shfl_xor_sync(0xffffffffu, a, o);
            c += __shfl_xor_sync(0xffffffffu, c, o);
        }
        if (!lane) { wsum[warp] = a; wsum2[warp] = c; }
        __syncthreads();
        if (tid == 0) {
            float sa = 0.f, sb = 0.f;
#pragma unroll
            for (int q = 0; q < 20; q++) { sa += wsum[q]; sb += wsum2[q]; }
            sc[0] = 1.f / fmaxf(sqrtf(sa), 1e-12f);
            sc[1] = sb;
        }
        __syncthreads();
    }

    const float inv_norm = sc[0];
    for (int d = tid; d < Dd; d += 640) {
        float v = d_ghat[d] * inv_norm;
#pragma unroll
        for (int r = 1; r < Rr; r++) v += goals[(size_t)r * Dd + d];
        gsum[d] = v;
    }
    __syncthreads();

    if (warp < NAa) {
        float v = wdot<16>((const float4*)(d_T + (size_t)warp * Dd),
                           (const float4*)gsum, lane);
        if (!lane) out[warp] = v;
    } else if (warp == NAa) {
        const float* st = states + (size_t)Rr * Dd;
        float num = 0.f, dd = 0.f, gg = 0.f;
        for (int d = lane; d < Dd; d += 32) {
            float diff = d_s[d] - st[d];
            float go = d_ghat[d] * inv_norm;
            num = fmaf(diff, go, num);
            dd = fmaf(diff, diff, dd);
            gg = fmaf(go, go, gg);
        }
#pragma unroll
        for (int o = 16; o; o >>= 1) {
            num += __shfl_xor_sync(0xffffffffu, num, o);
            dd += __shfl_xor_sync(0xffffffffu, dd, o);
            gg += __shfl_xor_sync(0xffffffffu, gg, o);
        }
        if (!lane)
            sc[2] = num / (fmaxf(sqrtf(dd), 1e-8f) * fmaxf(sqrtf(gg), 1e-8f));
    }
    __syncthreads();
    if (tid == 0) {
        float cs = sc[2];
#pragma unroll
        for (int r = 0; r < Rr - 1; r++) cs += d_cosv[r];
        out[18] = 2048.f * cs * 0.1f;
        out[19] = d_wval;
        out[20] = sc[1] + bmv[0];
    }
}

// ---------------- launch ------------------------------------------------------
extern "C" void kernel_launch(void* const* d_in, const int* in_sizes, int n_in,
                              void* d_out, int out_size) {
    const float* x      = (const float*)d_in[0];
    const float* Wp     = (const float*)d_in[1];
    const float* bp     = (const float*)d_in[2];
    const float* Wms    = (const float*)d_in[3];
    const float* bms    = (const float*)d_in[4];
    const float* Wih_m  = (const float*)d_in[5];
    const float* Whh_m  = (const float*)d_in[6];
    const float* bih_m  = (const float*)d_in[7];
    const float* bhh_m  = (const float*)d_in[8];
    const float* hn_m   = (const float*)d_in[9];
    const float* cn_m   = (const float*)d_in[10];
    const float* Wmv    = (const float*)d_in[11];
    const float* bmv    = (const float*)d_in[12];
    const float* Wih_w  = (const float*)d_in[13];
    const float* Whh_w  = (const float*)d_in[14];
    const float* bih_w  = (const float*)d_in[15];
    const float* bhh_w  = (const float*)d_in[16];
    const float* hn_w   = (const float*)d_in[17];
    const float* cn_w   = (const float*)d_in[18];
    const float* Wphi   = (const float*)d_in[19];
    const float* Wc     = (const float*)d_in[20];
    const float* bc     = (const float*)d_in[21];
    const float* states = (const float*)d_in[22];
    const float* goals  = (const float*)d_in[23];
    const int*   tick   = (const int*)d_in[24];
    float* out = (float*)d_out;

    kA<<<1856, 256>>>(x, Wp, bp, Wms, bms, Wih_w, Whh_w, bih_w, bhh_w,
                      hn_w, cn_w, Whh_m, bih_m, bhh_m, hn_m, tick);
    kB<<<1044, 256>>>(Wih_m, hn_m, cn_m, Wmv, Wphi, goals, states, Wc, bc,
                      tick);
    k4_final<<<1, 640>>>(goals, states, bmv, out);
}

// round 5
// speedup vs baseline: 1.2892x; 1.2892x over previous
#include <cuda_runtime.h>
#include <math.h>

#define Dd 2048
#define Hh 1152
#define Kk 64
#define NAa 18
#define Rr 10

// ---------------- scratch (device globals) ----------------------------------
__device__ __align__(16) float d_s[Dd];
__device__ __align__(16) float d_u[Hh];
__device__ __align__(16) float d_ghat[Dd];
__device__ __align__(16) float d_gpart[4 * Dd];   // Whh_m@h_t + biases
__device__ __align__(16) float d_T[NAa * Dd];     // u_resh @ Wphi
__device__ __align__(16) float d_hsum[Dd];        // sum_r hn_m[r]
__device__ __align__(16) float d_goalsum[Dd];     // sum_{r=1..9} goals[r]
__device__ float d_part_sq[1024];
__device__ float d_part_mv[1024];
__device__ float d_cosv[Rr];
__device__ float d_wval;

__device__ __forceinline__ float sigm(float x) { return 1.f / (1.f + expf(-x)); }

// warp dot over NIT*32 float4s (lane-strided), result on all lanes
template <int NIT>
__device__ __forceinline__ float wdot(const float4* __restrict__ a,
                                      const float4* __restrict__ b, int lane) {
    float acc = 0.f;
#pragma unroll
    for (int i = 0; i < NIT; i++) {
        float4 x = a[lane + i * 32];
        float4 y = b[lane + i * 32];
        acc = fmaf(x.x, y.x, acc);
        acc = fmaf(x.y, y.y, acc);
        acc = fmaf(x.z, y.z, acc);
        acc = fmaf(x.w, y.w, acc);
    }
#pragma unroll
    for (int o = 16; o; o >>= 1) acc += __shfl_xor_sync(0xffffffffu, acc, o);
    return acc;
}

// ---------------- Wave A -----------------------------------------------------
// blocks [0,256):      s rows, 1 row/warp
// blocks [256,832):    worker gate rows, 1 row/warp, 2 units/block
// blocks [832,1856):   Whh_m rows -> d_gpart, 1 row/warp
// blocks [1856,1864):  hsum
// blocks [1864,1872):  goalsum
__global__ void __launch_bounds__(256)
kA(const float* __restrict__ x, const float* __restrict__ Wp,
   const float* __restrict__ bp, const float* __restrict__ Wms,
   const float* __restrict__ bms, const float* __restrict__ Wih_w,
   const float* __restrict__ Whh_w, const float* __restrict__ bih_w,
   const float* __restrict__ bhh_w, const float* __restrict__ hn_w,
   const float* __restrict__ cn_w, const float* __restrict__ Whh_m,
   const float* __restrict__ bih_m, const float* __restrict__ bhh_m,
   const float* __restrict__ hn_m, const float* __restrict__ goals,
   const int* __restrict__ tickp) {
    const int warp = threadIdx.x >> 5, lane = threadIdx.x & 31;
    const int b = blockIdx.x;
    __shared__ __align__(16) float zs[Dd];
    __shared__ float gsh[8];

    if (b < 832) {
        // z = relu(Wp@x + bp) recomputed into smem
        float x0 = x[0], x1 = x[1];
        for (int i = threadIdx.x; i < Dd; i += 256) {
            float v = fmaf(Wp[2 * i], x0, fmaf(Wp[2 * i + 1], x1, bp[i]));
            zs[i] = fmaxf(v, 0.f);
        }
        __syncthreads();
        if (b < 256) {
            int row = b * 8 + warp;
            float v = wdot<16>((const float4*)(Wms + (size_t)row * Dd),
                               (const float4*)zs, lane);
            if (!lane) d_s[row] = fmaxf(v + bms[row], 0.f);
        } else {
            const int wb = b - 256;
            const int unit = wb * 2 + (warp >> 2);
            const int q = warp & 3;
            const int row = unit + q * Hh;
            float a = wdot<16>((const float4*)(Wih_w + (size_t)row * Dd),
                               (const float4*)zs, lane);
            float c = wdot<9>((const float4*)(Whh_w + (size_t)row * Hh),
                              (const float4*)hn_w, lane);
            if (!lane) gsh[warp] = a + c + bih_w[row] + bhh_w[row];
            __syncthreads();
            if ((threadIdx.x & 127) == 0) {
                const int half = threadIdx.x >> 7;
                const int j = wb * 2 + half;
                const float* g = gsh + half * 4;
                float ig = sigm(g[0]), fg = sigm(g[1]);
                float g2 = tanhf(g[2]), og = sigm(g[3]);
                float c2 = fmaf(fg, cn_w[j], ig * g2);
                d_u[j] = og * tanhf(c2);
            }
        }
    } else if (b < 1856) {
        const int tick = *tickp;
        const int row = (b - 832) * 8 + warp;
        float v = wdot<16>((const float4*)(Whh_m + (size_t)row * Dd),
                           (const float4*)(hn_m + (size_t)tick * Dd), lane);
        if (!lane) d_gpart[row] = v + bih_m[row] + bhh_m[row];
    } else if (b < 1864) {
        const int i = (b - 1856) * 256 + threadIdx.x;
        float a = 0.f;
#pragma unroll
        for (int r = 0; r < Rr; r++) a += hn_m[(size_t)r * Dd + i];
        d_hsum[i] = a;
    } else {
        const int d = (b - 1864) * 256 + threadIdx.x;
        float a = 0.f;
#pragma unroll
        for (int r = 1; r < Rr; r++) a += goals[(size_t)r * Dd + d];
        d_goalsum[d] = a;
    }
}

// ---------------- Wave B -----------------------------------------------------
// blocks [0,1024):     manager gate rows (1/warp, 2 units/block) -> ghat, partials
// blocks [1024,1042):  T row a = b-1024
// block  1042:         cosines r=0..8
// block  1043:         w_value
__global__ void __launch_bounds__(256)
kB(const float* __restrict__ Wih_m, const float* __restrict__ hn_m,
   const float* __restrict__ cn_m, const float* __restrict__ Wmv,
   const float* __restrict__ Wphi, const float* __restrict__ goals,
   const float* __restrict__ states, const float* __restrict__ Wc,
   const float* __restrict__ bc, const int* __restrict__ tickp) {
    const int tid = threadIdx.x;
    const int warp = tid >> 5, lane = tid & 31;
    const int b = blockIdx.x;

    if (b < 1024) {
        const int unit = b * 2 + (warp >> 2);
        const int q = warp & 3;
        const int row = unit + q * Dd;
        float v = wdot<16>((const float4*)(Wih_m + (size_t)row * Dd),
                           (const float4*)d_s, lane) + d_gpart[row];
        __shared__ float gsh[8];
        __shared__ float pp[4];
        if (!lane) gsh[warp] = v;
        __syncthreads();
        if ((tid & 127) == 0) {
            const int half = tid >> 7;
            const int i = b * 2 + half;
            const int tick = *tickp;
            const float* g = gsh + half * 4;
            float ig = sigm(g[0]), fg = sigm(g[1]);
            float g2 = tanhf(g[2]), og = sigm(g[3]);
            float c2 = fmaf(fg, cn_m[(size_t)tick * Dd + i], ig * g2);
            float hnew = og * tanhf(c2);
            float hs = d_hsum[i] - hn_m[(size_t)tick * Dd + i] + hnew;
            float gh = hs * 0.1f;
            d_ghat[i] = gh;
            pp[half * 2] = gh * gh;
            pp[half * 2 + 1] = gh * Wmv[i];
        }
        __syncthreads();
        if (tid == 0) {
            d_part_sq[b] = pp[0] + pp[2];
            d_part_mv[b] = pp[1] + pp[3];
        }
    } else if (b < 1024 + NAa) {
        const int a = b - 1024;
        __shared__ float us[Kk];
        if (tid < Kk) us[tid] = d_u[a * Kk + tid];
        __syncthreads();
        for (int d = tid; d < Dd; d += 256) {
            float acc = 0.f;
#pragma unroll 8
            for (int k = 0; k < Kk; k++)
                acc = fmaf(us[k], Wphi[(size_t)k * Dd + d], acc);
            d_T[(size_t)a * Dd + d] = acc;
        }
    } else if (b == 1024 + NAa) {
        for (int r = warp; r < Rr - 1; r += 8) {
            const float* st = states + (size_t)(r + 1) * Dd;
            const float* gl = goals + (size_t)(r + 1) * Dd;
            float num = 0.f, dd = 0.f, gg = 0.f;
            for (int d = lane; d < Dd; d += 32) {
                float diff = d_s[d] - st[d];
                float go = gl[d];
                num = fmaf(diff, go, num);
                dd = fmaf(diff, diff, dd);
                gg = fmaf(go, go, gg);
            }
#pragma unroll
            for (int o = 16; o; o >>= 1) {
                num += __shfl_xor_sync(0xffffffffu, num, o);
                dd += __shfl_xor_sync(0xffffffffu, dd, o);
                gg += __shfl_xor_sync(0xffffffffu, gg, o);
            }
            if (!lane)
                d_cosv[r] = num / (fmaxf(sqrtf(dd), 1e-8f) *
                                   fmaxf(sqrtf(gg), 1e-8f));
        }
    } else {
        __shared__ float red[256];
        float wv = 0.f;
        for (int j = tid; j < Hh; j += 256) wv = fmaf(d_u[j], Wc[j], wv);
        red[tid] = wv;
        __syncthreads();
        for (int s = 128; s; s >>= 1) {
            if (tid < s) red[tid] += red[tid + s];
            __syncthreads();
        }
        if (tid == 0) d_wval = red[0] + bc[0];
    }
}

// ---------------- K4: final (1 block, 640 threads) ---------------------------
// out: [0:18] logits, [18] intrinsic, [19] w_value, [20] m_value
__global__ void __launch_bounds__(640)
k4_final(const float* __restrict__ states, const float* __restrict__ bmv,
         float* __restrict__ out) {
    const int tid = threadIdx.x;
    const int warp = tid >> 5, lane = tid & 31;
    __shared__ float wsum[20], wsum2[20];
    __shared__ float sc[4];
    __shared__ __align__(16) float gsum[Dd];

    // reduce 1024 partials (sq and mv) deterministically
    {
        float a = 0.f, c = 0.f;
        for (int i = tid; i < 1024; i += 640) {
            a += d_part_sq[i];
            c += d_part_mv[i];
        }
#pragma unroll
        for (int o = 16; o; o >>= 1) {
            a += __shfl_xor_sync(0xffffffffu, a, o);
            c += __shfl_xor_sync(0xffffffffu, c, o);
        }
        if (!lane) { wsum[warp] = a; wsum2[warp] = c; }
        __syncthreads();
        if (tid == 0) {
            float sa = 0.f, sb = 0.f;
#pragma unroll
            for (int q = 0; q < 20; q++) { sa += wsum[q]; sb += wsum2[q]; }
            sc[0] = 1.f / fmaxf(sqrtf(sa), 1e-12f);
            sc[1] = sb;
        }
        __syncthreads();
    }

    const float inv_norm = sc[0];
    for (int d = tid; d < Dd; d += 640)
        gsum[d] = fmaf(d_ghat[d], inv_norm, d_goalsum[d]);
    __syncthreads();

    if (warp < NAa) {
        float v = wdot<16>((const float4*)(d_T + (size_t)warp * Dd),
                           (const float4*)gsum, lane);
        if (!lane) out[warp] = v;
    } else if (warp == NAa) {
        const float* st = states + (size_t)Rr * Dd;
        float num = 0.f, dd = 0.f, gg = 0.f;
        for (int d = lane; d < Dd; d += 32) {
            float diff = d_s[d] - st[d];
            float go = d_ghat[d] * inv_norm;
            num = fmaf(diff, go, num);
            dd = fmaf(diff, diff, dd);
            gg = fmaf(go, go, gg);
        }
#pragma unroll
        for (int o = 16; o; o >>= 1) {
            num += __shfl_xor_sync(0xffffffffu, num, o);
            dd += __shfl_xor_sync(0xffffffffu, dd, o);
            gg += __shfl_xor_sync(0xffffffffu, gg, o);
        }
        if (!lane)
            sc[2] = num / (fmaxf(sqrtf(dd), 1e-8f) * fmaxf(sqrtf(gg), 1e-8f));
    }
    __syncthreads();
    if (tid == 0) {
        float cs = sc[2];
#pragma unroll
        for (int r = 0; r < Rr - 1; r++) cs += d_cosv[r];
        out[18] = 2048.f * cs * 0.1f;
        out[19] = d_wval;
        out[20] = sc[1] + bmv[0];
    }
}

// ---------------- launch ------------------------------------------------------
extern "C" void kernel_launch(void* const* d_in, const int* in_sizes, int n_in,
                              void* d_out, int out_size) {
    const float* x      = (const float*)d_in[0];
    const float* Wp     = (const float*)d_in[1];
    const float* bp     = (const float*)d_in[2];
    const float* Wms    = (const float*)d_in[3];
    const float* bms    = (const float*)d_in[4];
    const float* Wih_m  = (const float*)d_in[5];
    const float* Whh_m  = (const float*)d_in[6];
    const float* bih_m  = (const float*)d_in[7];
    const float* bhh_m  = (const float*)d_in[8];
    const float* hn_m   = (const float*)d_in[9];
    const float* cn_m   = (const float*)d_in[10];
    const float* Wmv    = (const float*)d_in[11];
    const float* bmv    = (const float*)d_in[12];
    const float* Wih_w  = (const float*)d_in[13];
    const float* Whh_w  = (const float*)d_in[14];
    const float* bih_w  = (const float*)d_in[15];
    const float* bhh_w  = (const float*)d_in[16];
    const float* hn_w   = (const float*)d_in[17];
    const float* cn_w   = (const float*)d_in[18];
    const float* Wphi   = (const float*)d_in[19];
    const float* Wc     = (const float*)d_in[20];
    const float* bc     = (const float*)d_in[21];
    const float* states = (const float*)d_in[22];
    const float* goals  = (const float*)d_in[23];
    const int*   tick   = (const int*)d_in[24];
    float* out = (float*)d_out;

    kA<<<1872, 256>>>(x, Wp, bp, Wms, bms, Wih_w, Whh_w, bih_w, bhh_w,
                      hn_w, cn_w, Whh_m, bih_m, bhh_m, hn_m, goals, tick);
    kB<<<1044, 256>>>(Wih_m, hn_m, cn_m, Wmv, Wphi, goals, states, Wc, bc,
                      tick);
    k4_final<<<1, 640>>>(states, bmv, out);
}

// round 6
// speedup vs baseline: 1.4829x; 1.1503x over previous
#include <cuda_runtime.h>
#include <math.h>

#define Dd 2048
#define Hh 1152
#define Kk 64
#define NAa 18
#define Rr 10

// ---------------- scratch (device globals) ----------------------------------
__device__ __align__(16) float d_s[Dd];
__device__ __align__(16) float d_u[Hh];
__device__ __align__(16) float d_gpart[4 * Dd];   // Whh_m@h_t + biases
__device__ __align__(16) float d_gact[4 * Dd];    // full manager gate preact
__device__ __align__(16) float d_T[NAa * Dd];     // u_resh @ Wphi
__device__ __align__(16) float d_hsum[Dd];        // sum_r hn_m[r]
__device__ __align__(16) float d_goalsum[Dd];     // sum_{r=1..9} goals[r]
__device__ float d_cosv[Rr];
__device__ float d_wval;

__device__ __forceinline__ float sigm(float x) { return 1.f / (1.f + expf(-x)); }

// warp dot over NIT*32 float4s (lane-strided), result on all lanes
template <int NIT>
__device__ __forceinline__ float wdot(const float4* __restrict__ a,
                                      const float4* __restrict__ b, int lane) {
    float acc = 0.f;
#pragma unroll
    for (int i = 0; i < NIT; i++) {
        float4 x = a[lane + i * 32];
        float4 y = b[lane + i * 32];
        acc = fmaf(x.x, y.x, acc);
        acc = fmaf(x.y, y.y, acc);
        acc = fmaf(x.z, y.z, acc);
        acc = fmaf(x.w, y.w, acc);
    }
#pragma unroll
    for (int o = 16; o; o >>= 1) acc += __shfl_xor_sync(0xffffffffu, acc, o);
    return acc;
}

// ---------------- Wave A -----------------------------------------------------
// blocks [0,256):      s rows, 1 row/warp
// blocks [256,832):    worker gate rows, 1 row/warp, 2 units/block
// blocks [832,1856):   Whh_m rows -> d_gpart, 1 row/warp
// blocks [1856,1864):  hsum
// blocks [1864,1872):  goalsum
__global__ void __launch_bounds__(256)
kA(const float* __restrict__ x, const float* __restrict__ Wp,
   const float* __restrict__ bp, const float* __restrict__ Wms,
   const float* __restrict__ bms, const float* __restrict__ Wih_w,
   const float* __restrict__ Whh_w, const float* __restrict__ bih_w,
   const float* __restrict__ bhh_w, const float* __restrict__ hn_w,
   const float* __restrict__ cn_w, const float* __restrict__ Whh_m,
   const float* __restrict__ bih_m, const float* __restrict__ bhh_m,
   const float* __restrict__ hn_m, const float* __restrict__ goals,
   const int* __restrict__ tickp) {
    const int warp = threadIdx.x >> 5, lane = threadIdx.x & 31;
    const int b = blockIdx.x;
    __shared__ __align__(16) float zs[Dd];
    __shared__ float gsh[8];

    if (b < 832) {
        float x0 = x[0], x1 = x[1];
        for (int i = threadIdx.x; i < Dd; i += 256) {
            float v = fmaf(Wp[2 * i], x0, fmaf(Wp[2 * i + 1], x1, bp[i]));
            zs[i] = fmaxf(v, 0.f);
        }
        __syncthreads();
        if (b < 256) {
            int row = b * 8 + warp;
            float v = wdot<16>((const float4*)(Wms + (size_t)row * Dd),
                               (const float4*)zs, lane);
            if (!lane) d_s[row] = fmaxf(v + bms[row], 0.f);
        } else {
            const int wb = b - 256;
            const int unit = wb * 2 + (warp >> 2);
            const int q = warp & 3;
            const int row = unit + q * Hh;
            float a = wdot<16>((const float4*)(Wih_w + (size_t)row * Dd),
                               (const float4*)zs, lane);
            float c = wdot<9>((const float4*)(Whh_w + (size_t)row * Hh),
                              (const float4*)hn_w, lane);
            if (!lane) gsh[warp] = a + c + bih_w[row] + bhh_w[row];
            __syncthreads();
            if ((threadIdx.x & 127) == 0) {
                const int half = threadIdx.x >> 7;
                const int j = wb * 2 + half;
                const float* g = gsh + half * 4;
                float ig = sigm(g[0]), fg = sigm(g[1]);
                float g2 = tanhf(g[2]), og = sigm(g[3]);
                float c2 = fmaf(fg, cn_w[j], ig * g2);
                d_u[j] = og * tanhf(c2);
            }
        }
    } else if (b < 1856) {
        const int tick = *tickp;
        const int row = (b - 832) * 8 + warp;
        float v = wdot<16>((const float4*)(Whh_m + (size_t)row * Dd),
                           (const float4*)(hn_m + (size_t)tick * Dd), lane);
        if (!lane) d_gpart[row] = v + bih_m[row] + bhh_m[row];
    } else if (b < 1864) {
        const int i = (b - 1856) * 256 + threadIdx.x;
        float a = 0.f;
#pragma unroll
        for (int r = 0; r < Rr; r++) a += hn_m[(size_t)r * Dd + i];
        d_hsum[i] = a;
    } else {
        const int d = (b - 1864) * 256 + threadIdx.x;
        float a = 0.f;
#pragma unroll
        for (int r = 1; r < Rr; r++) a += goals[(size_t)r * Dd + d];
        d_goalsum[d] = a;
    }
}

// ---------------- Wave B (barrier-free streaming) ----------------------------
// blocks [0,1024):     manager gate rows, 1/warp -> d_gact (NO tail, NO barrier)
// blocks [1024,1032):  T columns: 256 d/block, u in smem, Wphi streamed once
// block  1032:         cosines r=0..8
// block  1033:         w_value
__global__ void __launch_bounds__(256)
kB(const float* __restrict__ Wih_m, const float* __restrict__ Wphi,
   const float* __restrict__ goals, const float* __restrict__ states,
   const float* __restrict__ Wc, const float* __restrict__ bc) {
    const int tid = threadIdx.x;
    const int warp = tid >> 5, lane = tid & 31;
    const int b = blockIdx.x;

    if (b < 1024) {
        const int row = b * 8 + warp;
        float v = wdot<16>((const float4*)(Wih_m + (size_t)row * Dd),
                           (const float4*)d_s, lane);
        if (!lane) d_gact[row] = v + d_gpart[row];
    } else if (b < 1024 + 8) {
        __shared__ float us[NAa * Kk];
        for (int i = tid; i < NAa * Kk; i += 256) us[i] = d_u[i];
        __syncthreads();
        const int d = (b - 1024) * 256 + tid;
        float acc[NAa];
#pragma unroll
        for (int a = 0; a < NAa; a++) acc[a] = 0.f;
        for (int k = 0; k < Kk; k++) {
            float w = Wphi[(size_t)k * Dd + d];
#pragma unroll
            for (int a = 0; a < NAa; a++)
                acc[a] = fmaf(us[a * Kk + k], w, acc[a]);
        }
#pragma unroll
        for (int a = 0; a < NAa; a++) d_T[(size_t)a * Dd + d] = acc[a];
    } else if (b == 1024 + 8) {
        for (int r = warp; r < Rr - 1; r += 8) {
            const float* st = states + (size_t)(r + 1) * Dd;
            const float* gl = goals + (size_t)(r + 1) * Dd;
            float num = 0.f, dd = 0.f, gg = 0.f;
            for (int d = lane; d < Dd; d += 32) {
                float diff = d_s[d] - st[d];
                float go = gl[d];
                num = fmaf(diff, go, num);
                dd = fmaf(diff, diff, dd);
                gg = fmaf(go, go, gg);
            }
#pragma unroll
            for (int o = 16; o; o >>= 1) {
                num += __shfl_xor_sync(0xffffffffu, num, o);
                dd += __shfl_xor_sync(0xffffffffu, dd, o);
                gg += __shfl_xor_sync(0xffffffffu, gg, o);
            }
            if (!lane)
                d_cosv[r] = num / (fmaxf(sqrtf(dd), 1e-8f) *
                                   fmaxf(sqrtf(gg), 1e-8f));
        }
    } else {
        __shared__ float red[256];
        float wv = 0.f;
        for (int j = tid; j < Hh; j += 256) wv = fmaf(d_u[j], Wc[j], wv);
        red[tid] = wv;
        __syncthreads();
        for (int s = 128; s; s >>= 1) {
            if (tid < s) red[tid] += red[tid + s];
            __syncthreads();
        }
        if (tid == 0) d_wval = red[0] + bc[0];
    }
}

// ---------------- K4: final (1 block, 1024 threads) --------------------------
// pointwise manager cell + reductions + gsum + logits + last cosine + outputs
// out: [0:18] logits, [18] intrinsic, [19] w_value, [20] m_value
__global__ void __launch_bounds__(1024)
k4_final(const float* __restrict__ hn_m, const float* __restrict__ cn_m,
         const float* __restrict__ Wmv, const float* __restrict__ states,
         const float* __restrict__ bmv, const int* __restrict__ tickp,
         float* __restrict__ out) {
    const int tid = threadIdx.x;
    const int warp = tid >> 5, lane = tid & 31;
    __shared__ float wsum[32], wsum2[32];
    __shared__ float sc[4];
    __shared__ __align__(16) float ghat_s[Dd];
    __shared__ __align__(16) float gsum[Dd];

    // phase 1: LSTM pointwise -> ghat, accumulate sq / mv
    const int tick = *tickp;
    float acc_sq = 0.f, acc_mv = 0.f;
#pragma unroll
    for (int rep = 0; rep < 2; rep++) {
        const int i = tid + rep * 1024;
        float g0 = d_gact[i];
        float g1 = d_gact[i + Dd];
        float g2 = d_gact[i + 2 * Dd];
        float g3 = d_gact[i + 3 * Dd];
        float ig = sigm(g0), fg = sigm(g1);
        float gt = tanhf(g2), og = sigm(g3);
        float c2 = fmaf(fg, cn_m[(size_t)tick * Dd + i], ig * gt);
        float hnew = og * tanhf(c2);
        float hs = d_hsum[i] - hn_m[(size_t)tick * Dd + i] + hnew;
        float gh = hs * 0.1f;
        ghat_s[i] = gh;
        acc_sq = fmaf(gh, gh, acc_sq);
        acc_mv = fmaf(gh, Wmv[i], acc_mv);
    }
#pragma unroll
    for (int o = 16; o; o >>= 1) {
        acc_sq += __shfl_xor_sync(0xffffffffu, acc_sq, o);
        acc_mv += __shfl_xor_sync(0xffffffffu, acc_mv, o);
    }
    if (!lane) { wsum[warp] = acc_sq; wsum2[warp] = acc_mv; }
    __syncthreads();
    if (tid == 0) {
        float sa = 0.f, sb = 0.f;
#pragma unroll
        for (int q = 0; q < 32; q++) { sa += wsum[q]; sb += wsum2[q]; }
        sc[0] = 1.f / fmaxf(sqrtf(sa), 1e-12f);
        sc[1] = sb;
    }
    __syncthreads();

    const float inv_norm = sc[0];
    for (int d = tid; d < Dd; d += 1024)
        gsum[d] = fmaf(ghat_s[d], inv_norm, d_goalsum[d]);
    __syncthreads();

    if (warp < NAa) {
        float v = wdot<16>((const float4*)(d_T + (size_t)warp * Dd),
                           (const float4*)gsum, lane);
        if (!lane) out[warp] = v;
    } else if (warp == NAa) {
        const float* st = states + (size_t)Rr * Dd;
        float num = 0.f, dd = 0.f, gg = 0.f;
        for (int d = lane; d < Dd; d += 32) {
            float diff = d_s[d] - st[d];
            float go = ghat_s[d] * inv_norm;
            num = fmaf(diff, go, num);
            dd = fmaf(diff, diff, dd);
            gg = fmaf(go, go, gg);
        }
#pragma unroll
        for (int o = 16; o; o >>= 1) {
            num += __shfl_xor_sync(0xffffffffu, num, o);
            dd += __shfl_xor_sync(0xffffffffu, dd, o);
            gg += __shfl_xor_sync(0xffffffffu, gg, o);
        }
        if (!lane)
            sc[2] = num / (fmaxf(sqrtf(dd), 1e-8f) * fmaxf(sqrtf(gg), 1e-8f));
    }
    __syncthreads();
    if (tid == 0) {
        float cs = sc[2];
#pragma unroll
        for (int r = 0; r < Rr - 1; r++) cs += d_cosv[r];
        out[18] = 2048.f * cs * 0.1f;
        out[19] = d_wval;
        out[20] = sc[1] + bmv[0];
    }
}

// ---------------- launch ------------------------------------------------------
extern "C" void kernel_launch(void* const* d_in, const int* in_sizes, int n_in,
                              void* d_out, int out_size) {
    const float* x      = (const float*)d_in[0];
    const float* Wp     = (const float*)d_in[1];
    const float* bp     = (const float*)d_in[2];
    const float* Wms    = (const float*)d_in[3];
    const float* bms    = (const float*)d_in[4];
    const float* Wih_m  = (const float*)d_in[5];
    const float* Whh_m  = (const float*)d_in[6];
    const float* bih_m  = (const float*)d_in[7];
    const float* bhh_m  = (const float*)d_in[8];
    const float* hn_m   = (const float*)d_in[9];
    const float* cn_m   = (const float*)d_in[10];
    const float* Wmv    = (const float*)d_in[11];
    const float* bmv    = (const float*)d_in[12];
    const float* Wih_w  = (const float*)d_in[13];
    const float* Whh_w  = (const float*)d_in[14];
    const float* bih_w  = (const float*)d_in[15];
    const float* bhh_w  = (const float*)d_in[16];
    const float* hn_w   = (const float*)d_in[17];
    const float* cn_w   = (const float*)d_in[18];
    const float* Wphi   = (const float*)d_in[19];
    const float* Wc     = (const float*)d_in[20];
    const float* bc     = (const float*)d_in[21];
    const float* states = (const float*)d_in[22];
    const float* goals  = (const float*)d_in[23];
    const int*   tick   = (const int*)d_in[24];
    float* out = (float*)d_out;

    kA<<<1872, 256>>>(x, Wp, bp, Wms, bms, Wih_w, Whh_w, bih_w, bhh_w,
                      hn_w, cn_w, Whh_m, bih_m, bhh_m, hn_m, goals, tick);
    kB<<<1034, 256>>>(Wih_m, Wphi, goals, states, Wc, bc);
    k4_final<<<1, 1024>>>(hn_m, cn_m, Wmv, states, bmv, tick, out);
}